// round 1
// baseline (speedup 1.0000x reference)
#include <cuda_runtime.h>
#include <math.h>

#define NN 10000
#define EE 160000
#define ET 170000   // edges + self loops

// ---------------- scratch (device globals; no allocations allowed) ----------
__device__ float g_h0  [NN * 512];
__device__ float g_hmat[NN * 2048];
__device__ float g_bufA[NN * 2048];
__device__ float g_bufB[NN * 2048];
__device__ float g_es  [NN * 4];
__device__ float g_ed  [NN * 4];
__device__ float g_alpha[ET * 4];
__device__ int   g_counts [NN];
__device__ int   g_rowptr [NN + 1];
__device__ int   g_fillpos[NN];
__device__ int   g_csrsrc [ET];
__device__ int   g_is64;

// ---------------- edge-index width detection (int64 vs int32) ---------------
__global__ void detect_kernel(const unsigned int* p) {
    int is64 = 1;
    for (int j = 0; j < 128; j++) {
        if (p[2 * j + 1] != 0u) { is64 = 0; break; }
    }
    g_is64 = is64;
}

__device__ __forceinline__ int edge_at(const void* ei, long long idx) {
    if (g_is64) return (int)((const long long*)ei)[idx];
    return ((const int*)ei)[idx];
}

// ---------------- CSR build ---------------------------------------------------
__global__ void init_counts_kernel() {
    int i = blockIdx.x * blockDim.x + threadIdx.x;
    if (i < NN) g_counts[i] = 1;   // self loop pre-counted
}

__global__ void count_kernel(const void* ei) {
    int e = blockIdx.x * blockDim.x + threadIdx.x;
    if (e < EE) {
        int d = edge_at(ei, (long long)EE + e);
        atomicAdd(&g_counts[d], 1);
    }
}

__global__ void scan_kernel() {
    __shared__ int sh[1024];
    int t = threadIdx.x;
    const int chunk = (NN + 1023) >> 10;   // 10
    int base = t * chunk;
    int s = 0;
    for (int j = 0; j < chunk; j++) {
        int idx = base + j;
        if (idx < NN) s += g_counts[idx];
    }
    sh[t] = s;
    __syncthreads();
    for (int off = 1; off < 1024; off <<= 1) {
        int v = (t >= off) ? sh[t - off] : 0;
        __syncthreads();
        sh[t] += v;
        __syncthreads();
    }
    int prefix = (t > 0) ? sh[t - 1] : 0;
    for (int j = 0; j < chunk; j++) {
        int idx = base + j;
        if (idx < NN) { g_rowptr[idx] = prefix; prefix += g_counts[idx]; }
    }
    if (t == 0) g_rowptr[NN] = sh[1023];
}

__global__ void fillself_kernel() {
    int i = blockIdx.x * blockDim.x + threadIdx.x;
    if (i < NN) {
        int r = g_rowptr[i];
        g_csrsrc[r] = i;          // self loop at row head (deterministic)
        g_fillpos[i] = r + 1;
    }
}

__global__ void filledges_kernel(const void* ei) {
    int e = blockIdx.x * blockDim.x + threadIdx.x;
    if (e < EE) {
        int s = edge_at(ei, e);
        int d = edge_at(ei, (long long)EE + e);
        int pos = atomicAdd(&g_fillpos[d], 1);
        g_csrsrc[pos] = s;
    }
}

// ---------------- fp32 tiled GEMM: C = A[MxK] @ B[KxN] (+bias) --------------
// 64x64 tile, BK=16, 256 threads, 4x4 per thread.
__global__ void gemm_kernel(const float* __restrict__ A, const float* __restrict__ B,
                            const float* __restrict__ bias, float* __restrict__ C,
                            int M, int N, int K) {
    __shared__ float As[16][64];
    __shared__ float Bs[16][64];

    int tid = threadIdx.x;
    int tx = tid & 15;          // 0..15 (cols)
    int ty = tid >> 4;          // 0..15 (rows)
    int rowBase = blockIdx.y * 64;
    int colBase = blockIdx.x * 64;

    int la_row = tid >> 2;            // 0..63
    int la_k4  = (tid & 3) * 4;       // 0,4,8,12
    int lb_k   = tid >> 4;            // 0..15
    int lb_c4  = (tid & 15) * 4;      // 0..60

    float acc[4][4];
#pragma unroll
    for (int r = 0; r < 4; r++)
#pragma unroll
        for (int c = 0; c < 4; c++) acc[r][c] = 0.f;

    for (int k0 = 0; k0 < K; k0 += 16) {
        int ar = rowBase + la_row;
        float4 av = make_float4(0.f, 0.f, 0.f, 0.f);
        if (ar < M) av = *(const float4*)(A + (size_t)ar * K + k0 + la_k4);
        As[la_k4 + 0][la_row] = av.x;
        As[la_k4 + 1][la_row] = av.y;
        As[la_k4 + 2][la_row] = av.z;
        As[la_k4 + 3][la_row] = av.w;

        float4 bv = *(const float4*)(B + (size_t)(k0 + lb_k) * N + colBase + lb_c4);
        *(float4*)&Bs[lb_k][lb_c4] = bv;
        __syncthreads();

#pragma unroll
        for (int kk = 0; kk < 16; kk++) {
            float4 a4 = *(float4*)&As[kk][ty * 4];
            float4 b4 = *(float4*)&Bs[kk][tx * 4];
            float ar_[4] = {a4.x, a4.y, a4.z, a4.w};
            float br_[4] = {b4.x, b4.y, b4.z, b4.w};
#pragma unroll
            for (int r = 0; r < 4; r++)
#pragma unroll
                for (int c = 0; c < 4; c++)
                    acc[r][c] += ar_[r] * br_[c];
        }
        __syncthreads();
    }

#pragma unroll
    for (int r = 0; r < 4; r++) {
        int row = rowBase + ty * 4 + r;
        if (row < M) {
#pragma unroll
            for (int c = 0; c < 4; c++) {
                int col = colBase + tx * 4 + c;
                float v = acc[r][c];
                if (bias) v += bias[col];
                C[(size_t)row * N + col] = v;
            }
        }
    }
}

// ---------------- per-node attention coefficients es/ed ---------------------
// grid = NN, block = 32*H. Warp hh handles head hh (C = 512).
__global__ void attn_kernel(const float* __restrict__ hmat,
                            const float* __restrict__ a_src,
                            const float* __restrict__ a_dst,
                            int H) {
    const int C = 512;
    int i = blockIdx.x;
    int hh = threadIdx.x >> 5;
    int lane = threadIdx.x & 31;
    const float* hr = hmat + (size_t)i * H * C + hh * C;
    float s = 0.f, d = 0.f;
    for (int c = lane; c < C; c += 32) {
        float v = hr[c];
        s += v * a_src[hh * C + c];
        d += v * a_dst[hh * C + c];
    }
#pragma unroll
    for (int o = 16; o > 0; o >>= 1) {
        s += __shfl_xor_sync(0xffffffffu, s, o);
        d += __shfl_xor_sync(0xffffffffu, d, o);
    }
    if (lane == 0) {
        g_es[i * H + hh] = s;
        g_ed[i * H + hh] = d;
    }
}

// ---------------- segment softmax over dst-CSR rows -------------------------
// one thread per (node, head); alpha stored at stride 4 in CSR edge order
__global__ void softmax_kernel(int H) {
    int idx = blockIdx.x * blockDim.x + threadIdx.x;
    if (idx >= NN * H) return;
    int i = idx % NN;
    int hh = idx / NN;
    float edi = g_ed[i * H + hh];
    int p0 = g_rowptr[i], p1 = g_rowptr[i + 1];

    float m = -1e30f;
    for (int p = p0; p < p1; p++) {
        float e = g_es[g_csrsrc[p] * H + hh] + edi;
        e = (e > 0.f) ? e : 0.2f * e;
        m = fmaxf(m, e);
    }
    float den = 0.f;
    for (int p = p0; p < p1; p++) {
        float e = g_es[g_csrsrc[p] * H + hh] + edi;
        e = (e > 0.f) ? e : 0.2f * e;
        float a = expf(e - m);
        g_alpha[p * 4 + hh] = a;
        den += a;
    }
    float inv = 1.f / den;
    for (int p = p0; p < p1; p++) g_alpha[p * 4 + hh] *= inv;
}

// ---------------- weighted aggregation over incoming edges ------------------
// MODE 0: concat heads, +bias, ELU.  MODE 1: mean over 2 heads, +bias.
// C fixed = 512; head of column (t + k*256) is k>>1 since t < 256.
template <int HC, int MODE>
__global__ void aggregate_kernel(const float* __restrict__ hmat,
                                 const float* __restrict__ bias,
                                 float* __restrict__ out) {
    constexpr int PT = HC / 256;
    int i = blockIdx.x;
    int t = threadIdx.x;
    float acc[PT];
#pragma unroll
    for (int k = 0; k < PT; k++) acc[k] = 0.f;

    int p0 = g_rowptr[i], p1 = g_rowptr[i + 1];
    for (int p = p0; p < p1; p++) {
        int s = g_csrsrc[p];
        float4 a4 = *(const float4*)(g_alpha + p * 4);
        float a[4] = {a4.x, a4.y, a4.z, a4.w};
        const float* hr = hmat + (size_t)s * HC;
#pragma unroll
        for (int k = 0; k < PT; k++)
            acc[k] += a[k >> 1] * hr[t + k * 256];
    }

    if (MODE == 0) {
#pragma unroll
        for (int k = 0; k < PT; k++) {
            int col = t + k * 256;
            float v = acc[k] + bias[col];
            out[(size_t)i * HC + col] = (v > 0.f) ? v : (expf(v) - 1.f);
        }
    } else {
        // PT == 4, heads = 2, mean then bias; output width 512
        float v0 = 0.5f * (acc[0] + acc[2]) + bias[t];
        float v1 = 0.5f * (acc[1] + acc[3]) + bias[t + 256];
        out[(size_t)i * 512 + t]       = v0;
        out[(size_t)i * 512 + t + 256] = v1;
    }
}

// ---------------- launch -----------------------------------------------------
static void launch_gemm(const float* A, const float* B, const float* bias,
                        float* C, int M, int N, int K) {
    dim3 grid(N / 64, (M + 63) / 64);
    gemm_kernel<<<grid, 256>>>(A, B, bias, C, M, N, K);
}

extern "C" void kernel_launch(void* const* d_in, const int* in_sizes, int n_in,
                              void* d_out, int out_size) {
    const float* x      = (const float*)d_in[0];
    const void*  ei     = d_in[1];
    const float* proj_w = (const float*)d_in[2];
    const float* proj_b = (const float*)d_in[3];
    const float* w1  = (const float*)d_in[4];
    const float* as1 = (const float*)d_in[5];
    const float* ad1 = (const float*)d_in[6];
    const float* b1  = (const float*)d_in[7];
    const float* w2  = (const float*)d_in[8];
    const float* as2 = (const float*)d_in[9];
    const float* ad2 = (const float*)d_in[10];
    const float* b2  = (const float*)d_in[11];
    const float* w3  = (const float*)d_in[12];
    const float* as3 = (const float*)d_in[13];
    const float* ad3 = (const float*)d_in[14];
    const float* b3  = (const float*)d_in[15];
    float* out = (float*)d_out;

    float *h0, *hmat, *bufA, *bufB;
    cudaGetSymbolAddress((void**)&h0,   g_h0);
    cudaGetSymbolAddress((void**)&hmat, g_hmat);
    cudaGetSymbolAddress((void**)&bufA, g_bufA);
    cudaGetSymbolAddress((void**)&bufB, g_bufB);

    // ---- CSR build (shared by all 3 layers) ----
    detect_kernel<<<1, 1>>>((const unsigned int*)ei);
    init_counts_kernel<<<(NN + 255) / 256, 256>>>();
    count_kernel<<<(EE + 255) / 256, 256>>>(ei);
    scan_kernel<<<1, 1024>>>();
    fillself_kernel<<<(NN + 255) / 256, 256>>>();
    filledges_kernel<<<(EE + 255) / 256, 256>>>(ei);

    // ---- projection: h0 = x @ proj_w + proj_b ----
    launch_gemm(x, proj_w, proj_b, h0, NN, 512, 256);

    // ---- GAT layer 1 (H=4, C=512, concat, ELU) ----
    launch_gemm(h0, w1, nullptr, hmat, NN, 2048, 512);
    attn_kernel<<<NN, 128>>>(hmat, as1, ad1, 4);
    softmax_kernel<<<(NN * 4 + 255) / 256, 256>>>(4);
    aggregate_kernel<2048, 0><<<NN, 256>>>(hmat, b1, bufA);

    // ---- GAT layer 2 (H=4, C=512, concat, ELU) ----
    launch_gemm(bufA, w2, nullptr, hmat, NN, 2048, 2048);
    attn_kernel<<<NN, 128>>>(hmat, as2, ad2, 4);
    softmax_kernel<<<(NN * 4 + 255) / 256, 256>>>(4);
    aggregate_kernel<2048, 0><<<NN, 256>>>(hmat, b2, bufB);

    // ---- GAT layer 3 (H=2, C=512, mean) ----
    launch_gemm(bufB, w3, nullptr, hmat, NN, 1024, 2048);
    attn_kernel<<<NN, 64>>>(hmat, as3, ad3, 2);
    softmax_kernel<<<(NN * 2 + 255) / 256, 256>>>(2);
    aggregate_kernel<1024, 1><<<NN, 256>>>(hmat, b3, out);
}

// round 3
// speedup vs baseline: 2.4377x; 2.4377x over previous
#include <cuda_runtime.h>
#include <cuda_bf16.h>
#include <math.h>
#include <stdint.h>

#define NN 10000
#define EE 160000
#define ET 170000   // edges + self loops

// ---------------- scratch (device globals; no allocations allowed) ----------
__device__ float g_h0  [NN * 512];
__device__ float g_hmat[NN * 2048];
__device__ float g_bufA[NN * 2048];
__device__ float g_bufB[NN * 2048];
__device__ float g_es  [NN * 4];
__device__ float g_ed  [NN * 4];
__device__ float g_alpha[ET * 4];
__device__ int   g_counts [NN];
__device__ int   g_rowptr [NN + 1];
__device__ int   g_fillpos[NN];
__device__ int   g_csrsrc [ET];
__device__ int   g_is64;
// bf16 hi/lo operand buffers
__device__ __align__(16) __nv_bfloat16 g_Ah[NN * 2048];
__device__ __align__(16) __nv_bfloat16 g_Al[NN * 2048];
__device__ __align__(16) __nv_bfloat16 g_Wh[2048 * 2048];
__device__ __align__(16) __nv_bfloat16 g_Wl[2048 * 2048];

// ============================ PTX helpers (baseline, sm_80+) =================
__device__ __forceinline__ uint32_t smem_to_u32(const void* p) {
    uint32_t a;
    asm("{ .reg .u64 t; cvta.to.shared.u64 t, %1; cvt.u32.u64 %0, t; }" : "=r"(a) : "l"(p));
    return a;
}

__device__ __forceinline__ void cp16(uint32_t dst, const void* src, bool v) {
    int sz = v ? 16 : 0;
    asm volatile("cp.async.cg.shared.global [%0], [%1], 16, %2;\n"
                 :: "r"(dst), "l"(src), "r"(sz) : "memory");
}
#define CP_COMMIT() asm volatile("cp.async.commit_group;" ::: "memory")
#define CP_WAIT1()  asm volatile("cp.async.wait_group 1;" ::: "memory")

__device__ __forceinline__ void ldsm4(uint32_t* r, uint32_t addr) {
    asm volatile("ldmatrix.sync.aligned.m8n8.x4.shared.b16 {%0,%1,%2,%3}, [%4];"
                 : "=r"(r[0]), "=r"(r[1]), "=r"(r[2]), "=r"(r[3]) : "r"(addr));
}

__device__ __forceinline__ void mma16816(float* c, const uint32_t* a, const uint32_t* b) {
    asm volatile(
        "mma.sync.aligned.m16n8k16.row.col.f32.bf16.bf16.f32 "
        "{%0,%1,%2,%3}, {%4,%5,%6,%7}, {%8,%9}, {%0,%1,%2,%3};"
        : "+f"(c[0]), "+f"(c[1]), "+f"(c[2]), "+f"(c[3])
        : "r"(a[0]), "r"(a[1]), "r"(a[2]), "r"(a[3]), "r"(b[0]), "r"(b[1]));
}

// ---------------- edge-index width detection (int64 vs int32) ---------------
__global__ void detect_kernel(const unsigned int* p) {
    int is64 = 1;
    for (int j = 0; j < 128; j++) {
        if (p[2 * j + 1] != 0u) { is64 = 0; break; }
    }
    g_is64 = is64;
}

__device__ __forceinline__ int edge_at(const void* ei, long long idx) {
    if (g_is64) return (int)((const long long*)ei)[idx];
    return ((const int*)ei)[idx];
}

// ---------------- CSR build --------------------------------------------------
__global__ void init_counts_kernel() {
    int i = blockIdx.x * blockDim.x + threadIdx.x;
    if (i < NN) g_counts[i] = 1;
}
__global__ void count_kernel(const void* ei) {
    int e = blockIdx.x * blockDim.x + threadIdx.x;
    if (e < EE) atomicAdd(&g_counts[edge_at(ei, (long long)EE + e)], 1);
}
__global__ void scan_kernel() {
    __shared__ int sh[1024];
    int t = threadIdx.x;
    const int chunk = (NN + 1023) >> 10;
    int base = t * chunk;
    int s = 0;
    for (int j = 0; j < chunk; j++) { int idx = base + j; if (idx < NN) s += g_counts[idx]; }
    sh[t] = s;
    __syncthreads();
    for (int off = 1; off < 1024; off <<= 1) {
        int v = (t >= off) ? sh[t - off] : 0;
        __syncthreads();
        sh[t] += v;
        __syncthreads();
    }
    int prefix = (t > 0) ? sh[t - 1] : 0;
    for (int j = 0; j < chunk; j++) {
        int idx = base + j;
        if (idx < NN) { g_rowptr[idx] = prefix; prefix += g_counts[idx]; }
    }
    if (t == 0) g_rowptr[NN] = sh[1023];
}
__global__ void fillself_kernel() {
    int i = blockIdx.x * blockDim.x + threadIdx.x;
    if (i < NN) { int r = g_rowptr[i]; g_csrsrc[r] = i; g_fillpos[i] = r + 1; }
}
__global__ void filledges_kernel(const void* ei) {
    int e = blockIdx.x * blockDim.x + threadIdx.x;
    if (e < EE) {
        int s = edge_at(ei, e);
        int d = edge_at(ei, (long long)EE + e);
        g_csrsrc[atomicAdd(&g_fillpos[d], 1)] = s;
    }
}

// ---------------- fp32 -> bf16 hi/lo split -----------------------------------
__global__ void cvt_split_kernel(const float* __restrict__ x,
                                 __nv_bfloat16* __restrict__ hi,
                                 __nv_bfloat16* __restrict__ lo, int n4) {
    int i = blockIdx.x * blockDim.x + threadIdx.x;
    if (i >= n4) return;
    float4 v = ((const float4*)x)[i];
    __nv_bfloat16 h0 = __float2bfloat16(v.x);
    __nv_bfloat16 h1 = __float2bfloat16(v.y);
    __nv_bfloat16 h2 = __float2bfloat16(v.z);
    __nv_bfloat16 h3 = __float2bfloat16(v.w);
    __nv_bfloat16 l0 = __float2bfloat16(v.x - __bfloat162float(h0));
    __nv_bfloat16 l1 = __float2bfloat16(v.y - __bfloat162float(h1));
    __nv_bfloat16 l2 = __float2bfloat16(v.z - __bfloat162float(h2));
    __nv_bfloat16 l3 = __float2bfloat16(v.w - __bfloat162float(h3));
    ((__nv_bfloat162*)hi)[2 * i]     = __nv_bfloat162(h0, h1);
    ((__nv_bfloat162*)hi)[2 * i + 1] = __nv_bfloat162(h2, h3);
    ((__nv_bfloat162*)lo)[2 * i]     = __nv_bfloat162(l0, l1);
    ((__nv_bfloat162*)lo)[2 * i + 1] = __nv_bfloat162(l2, l3);
}

// ---------------- weight transpose + split: W[K,N] -> Wt[N,K] hi/lo ----------
__global__ void cvt_transpose_kernel(const float* __restrict__ W,
                                     __nv_bfloat16* __restrict__ th,
                                     __nv_bfloat16* __restrict__ tl, int K, int N) {
    __shared__ float tile[32][33];
    int n0 = blockIdx.x * 32, k0 = blockIdx.y * 32;
    int tx = threadIdx.x, ty = threadIdx.y;   // 32 x 8
    for (int r = ty; r < 32; r += 8)
        tile[r][tx] = W[(size_t)(k0 + r) * N + n0 + tx];
    __syncthreads();
    for (int r = ty; r < 32; r += 8) {
        float v = tile[tx][r];   // = W[k0+tx][n0+r]
        __nv_bfloat16 h = __float2bfloat16(v);
        size_t o = (size_t)(n0 + r) * K + k0 + tx;
        th[o] = h;
        tl[o] = __float2bfloat16(v - __bfloat162float(h));
    }
}

// ---------------- mma.sync bf16x3 GEMM: C = A[M,K] @ Bt[N,K]^T (+bias) -------
// 128x128 CTA tile, BK=64, 3-stage cp.async pipeline, 8 warps of 64x32.
#define TILE_BYTES 16384                  // 128 rows x 128B (one operand tile)
#define STAGE_BYTES (4 * TILE_BYTES)      // Ah, Al, Bh, Bl
#define SMEM_TOTAL  (3 * STAGE_BYTES)     // 196608

__device__ __forceinline__ uint32_t swz(uint32_t base, int row, int kelem) {
    return base + row * 128 + ((((kelem >> 3) ^ row) & 7) << 4);
}

__device__ __forceinline__ void load_stage(
    uint32_t sbase,
    const __nv_bfloat16* __restrict__ Ah, const __nv_bfloat16* __restrict__ Al,
    const __nv_bfloat16* __restrict__ Bh, const __nv_bfloat16* __restrict__ Bl,
    int m0, int n0, int M, int K, int j, int nk, int tid)
{
    const int lrow = tid >> 3;            // 0..31
    const int lchk = tid & 7;             // 16B chunk within 128B row
    const bool jv = (j < nk);
    const long long k0 = jv ? ((long long)j << 6) : 0;
#pragma unroll
    for (int it = 0; it < 4; it++) {
        int row = lrow + it * 32;
        bool av = jv && (m0 + row < M);
        int gr = (m0 + row < M) ? (m0 + row) : 0;
        size_t aoff = (size_t)gr * K + k0 + lchk * 8;
        size_t boff = (size_t)(n0 + row) * K + k0 + lchk * 8;
        uint32_t d = swz(sbase, row, lchk * 8);
        cp16(d,                  Ah + aoff, av);
        cp16(d + TILE_BYTES,     Al + aoff, av);
        cp16(d + 2 * TILE_BYTES, Bh + boff, jv);
        cp16(d + 3 * TILE_BYTES, Bl + boff, jv);
    }
}

__global__ void __launch_bounds__(256, 1) gemm_mma_kernel(
    const __nv_bfloat16* __restrict__ Ah, const __nv_bfloat16* __restrict__ Al,
    const __nv_bfloat16* __restrict__ Bh, const __nv_bfloat16* __restrict__ Bl,
    const float* __restrict__ bias, float* __restrict__ C,
    int M, int N, int K)
{
    extern __shared__ char smem[];
    const uint32_t sb = smem_to_u32(smem);
    const int tid = threadIdx.x;
    const int lane = tid & 31, wid = tid >> 5;
    const int m0 = blockIdx.y * 128, n0 = blockIdx.x * 128;
    const int nk = K >> 6;

    float acc[4][4][4];
#pragma unroll
    for (int a = 0; a < 4; a++)
#pragma unroll
        for (int b = 0; b < 4; b++)
#pragma unroll
            for (int c = 0; c < 4; c++) acc[a][b][c] = 0.f;

    // prologue: stages 0, 1
    load_stage(sb,               Ah, Al, Bh, Bl, m0, n0, M, K, 0, nk, tid);
    CP_COMMIT();
    load_stage(sb + STAGE_BYTES, Ah, Al, Bh, Bl, m0, n0, M, K, 1, nk, tid);
    CP_COMMIT();

    const int mw = (wid & 1) * 64;    // warp M offset
    const int nw = (wid >> 1) * 32;   // warp N offset
    const int rsel = lane & 15;
    const int khalf = (lane >> 4) * 8;

    for (int i = 0; i < nk; i++) {
        CP_WAIT1();
        __syncthreads();
        // prefetch stage i+2 (zero-fill past the end)
        load_stage(sb + (uint32_t)((i + 2) % 3) * STAGE_BYTES,
                   Ah, Al, Bh, Bl, m0, n0, M, K, i + 2, nk, tid);
        CP_COMMIT();

        const uint32_t sA  = sb + (uint32_t)(i % 3) * STAGE_BYTES;
        const uint32_t sB  = sA + 2 * TILE_BYTES;
#pragma unroll
        for (int ks = 0; ks < 4; ks++) {
            uint32_t ah[4][4], al[4][4], bh[2][4], bl[2][4];
            const int ke = ks * 16 + khalf;
#pragma unroll
            for (int mi = 0; mi < 4; mi++) {
                uint32_t ad = swz(sA, mw + mi * 16 + rsel, ke);
                ldsm4(ah[mi], ad);
                ldsm4(al[mi], ad + TILE_BYTES);
            }
#pragma unroll
            for (int bi = 0; bi < 2; bi++) {
                uint32_t bd = swz(sB, nw + bi * 16 + rsel, ke);
                ldsm4(bh[bi], bd);
                ldsm4(bl[bi], bd + TILE_BYTES);
            }
#pragma unroll
            for (int mi = 0; mi < 4; mi++) {
#pragma unroll
                for (int nj = 0; nj < 4; nj++) {
                    uint32_t b2h[2] = { bh[nj >> 1][nj & 1], bh[nj >> 1][(nj & 1) + 2] };
                    uint32_t b2l[2] = { bl[nj >> 1][nj & 1], bl[nj >> 1][(nj & 1) + 2] };
                    mma16816(acc[mi][nj], ah[mi], b2h);
                    mma16816(acc[mi][nj], ah[mi], b2l);
                    mma16816(acc[mi][nj], al[mi], b2h);
                }
            }
        }
    }

    // epilogue: write fp32 (+bias)
#pragma unroll
    for (int mi = 0; mi < 4; mi++) {
#pragma unroll
        for (int nj = 0; nj < 4; nj++) {
            int col = n0 + nw + nj * 8 + (lane & 3) * 2;
            float bx = 0.f, by = 0.f;
            if (bias) { bx = bias[col]; by = bias[col + 1]; }
            int r0 = m0 + mw + mi * 16 + (lane >> 2);
            if (r0 < M) {
                float2 v = make_float2(acc[mi][nj][0] + bx, acc[mi][nj][1] + by);
                *(float2*)(C + (size_t)r0 * N + col) = v;
            }
            int r1 = r0 + 8;
            if (r1 < M) {
                float2 v = make_float2(acc[mi][nj][2] + bx, acc[mi][nj][3] + by);
                *(float2*)(C + (size_t)r1 * N + col) = v;
            }
        }
    }
}

// ---------------- per-node attention coefficients es/ed ----------------------
__global__ void attn_kernel(const float* __restrict__ hmat,
                            const float* __restrict__ a_src,
                            const float* __restrict__ a_dst, int H) {
    const int C = 512;
    int i = blockIdx.x;
    int hh = threadIdx.x >> 5;
    int lane = threadIdx.x & 31;
    const float* hr = hmat + (size_t)i * H * C + hh * C;
    float s = 0.f, d = 0.f;
    for (int c = lane; c < C; c += 32) {
        float v = hr[c];
        s += v * a_src[hh * C + c];
        d += v * a_dst[hh * C + c];
    }
#pragma unroll
    for (int o = 16; o > 0; o >>= 1) {
        s += __shfl_xor_sync(0xffffffffu, s, o);
        d += __shfl_xor_sync(0xffffffffu, d, o);
    }
    if (lane == 0) { g_es[i * H + hh] = s; g_ed[i * H + hh] = d; }
}

// ---------------- segment softmax over dst-CSR rows --------------------------
__global__ void softmax_kernel(int H) {
    int idx = blockIdx.x * blockDim.x + threadIdx.x;
    if (idx >= NN * H) return;
    int i = idx % NN;
    int hh = idx / NN;
    float edi = g_ed[i * H + hh];
    int p0 = g_rowptr[i], p1 = g_rowptr[i + 1];
    float m = -1e30f;
    for (int p = p0; p < p1; p++) {
        float e = g_es[g_csrsrc[p] * H + hh] + edi;
        e = (e > 0.f) ? e : 0.2f * e;
        m = fmaxf(m, e);
    }
    float den = 0.f;
    for (int p = p0; p < p1; p++) {
        float e = g_es[g_csrsrc[p] * H + hh] + edi;
        e = (e > 0.f) ? e : 0.2f * e;
        float a = expf(e - m);
        g_alpha[p * 4 + hh] = a;
        den += a;
    }
    float inv = 1.f / den;
    for (int p = p0; p < p1; p++) g_alpha[p * 4 + hh] *= inv;
}

// ---------------- weighted aggregation (float4) ------------------------------
// MODE 0: concat heads + bias + ELU. MODE 1: mean over 2 heads + bias.
template <int HC, int MODE>
__global__ void aggregate_kernel(const float* __restrict__ hmat,
                                 const float* __restrict__ bias,
                                 float* __restrict__ out) {
    constexpr int PT = HC / 1024;            // float4s per thread
    int i = blockIdx.x;
    int t = threadIdx.x;
    int hsel = t >> 7;                        // 0 or 1
    float4 acc[PT];
#pragma unroll
    for (int k = 0; k < PT; k++) acc[k] = make_float4(0.f, 0.f, 0.f, 0.f);

    int p0 = g_rowptr[i], p1 = g_rowptr[i + 1];
    for (int p = p0; p < p1; p++) {
        int s = g_csrsrc[p];
        float4 a4 = *(const float4*)(g_alpha + p * 4);
        const float* al = (const float*)&a4;
        const float4* hr = (const float4*)(hmat + (size_t)s * HC);
#pragma unroll
        for (int k = 0; k < PT; k++) {
            float av = al[2 * k + hsel];
            float4 h = hr[t + k * 256];
            acc[k].x += av * h.x;
            acc[k].y += av * h.y;
            acc[k].z += av * h.z;
            acc[k].w += av * h.w;
        }
    }

    if (MODE == 0) {
#pragma unroll
        for (int k = 0; k < PT; k++) {
            int col4 = t + k * 256;
            float4 b = *(const float4*)(bias + col4 * 4);
            float4 v = acc[k];
            v.x += b.x; v.y += b.y; v.z += b.z; v.w += b.w;
            v.x = (v.x > 0.f) ? v.x : (expf(v.x) - 1.f);
            v.y = (v.y > 0.f) ? v.y : (expf(v.y) - 1.f);
            v.z = (v.z > 0.f) ? v.z : (expf(v.z) - 1.f);
            v.w = (v.w > 0.f) ? v.w : (expf(v.w) - 1.f);
            ((float4*)out)[(size_t)i * (HC / 4) + col4] = v;
        }
    } else {
        __shared__ float4 sh[256];
        sh[t] = acc[0];
        __syncthreads();
        if (t < 128) {
            float4 v0 = sh[t], v1 = sh[t + 128];
            float4 b = ((const float4*)bias)[t];
            float4 r;
            r.x = 0.5f * (v0.x + v1.x) + b.x;
            r.y = 0.5f * (v0.y + v1.y) + b.y;
            r.z = 0.5f * (v0.z + v1.z) + b.z;
            r.w = 0.5f * (v0.w + v1.w) + b.w;
            ((float4*)out)[(size_t)i * 128 + t] = r;
        }
    }
}

// ---------------- host launch helpers ----------------------------------------
static void run_gemm(const __nv_bfloat16* ah, const __nv_bfloat16* al,
                     const __nv_bfloat16* wh, const __nv_bfloat16* wl,
                     const float* bias, float* C, int M, int N, int K) {
    dim3 grid(N / 128, (M + 127) / 128);
    gemm_mma_kernel<<<grid, 256, SMEM_TOTAL>>>(ah, al, wh, wl, bias, C, M, N, K);
}

extern "C" void kernel_launch(void* const* d_in, const int* in_sizes, int n_in,
                              void* d_out, int out_size) {
    const float* x      = (const float*)d_in[0];
    const void*  ei     = d_in[1];
    const float* proj_w = (const float*)d_in[2];
    const float* proj_b = (const float*)d_in[3];
    const float* w1  = (const float*)d_in[4];
    const float* as1 = (const float*)d_in[5];
    const float* ad1 = (const float*)d_in[6];
    const float* b1  = (const float*)d_in[7];
    const float* w2  = (const float*)d_in[8];
    const float* as2 = (const float*)d_in[9];
    const float* ad2 = (const float*)d_in[10];
    const float* b2  = (const float*)d_in[11];
    const float* w3  = (const float*)d_in[12];
    const float* as3 = (const float*)d_in[13];
    const float* ad3 = (const float*)d_in[14];
    const float* b3  = (const float*)d_in[15];
    float* out = (float*)d_out;

    float *h0, *hmat, *bufA, *bufB;
    __nv_bfloat16 *Ah, *Al, *Wh, *Wl;
    cudaGetSymbolAddress((void**)&h0,   g_h0);
    cudaGetSymbolAddress((void**)&hmat, g_hmat);
    cudaGetSymbolAddress((void**)&bufA, g_bufA);
    cudaGetSymbolAddress((void**)&bufB, g_bufB);
    cudaGetSymbolAddress((void**)&Ah, g_Ah);
    cudaGetSymbolAddress((void**)&Al, g_Al);
    cudaGetSymbolAddress((void**)&Wh, g_Wh);
    cudaGetSymbolAddress((void**)&Wl, g_Wl);

    static bool attr_set = false;
    if (!attr_set) {
        cudaFuncSetAttribute(gemm_mma_kernel,
                             cudaFuncAttributeMaxDynamicSharedMemorySize, SMEM_TOTAL);
        attr_set = true;
    }

    // ---- CSR build ----
    detect_kernel<<<1, 1>>>((const unsigned int*)ei);
    init_counts_kernel<<<(NN + 255) / 256, 256>>>();
    count_kernel<<<(EE + 255) / 256, 256>>>(ei);
    scan_kernel<<<1, 1024>>>();
    fillself_kernel<<<(NN + 255) / 256, 256>>>();
    filledges_kernel<<<(EE + 255) / 256, 256>>>(ei);

    // ---- projection: h0 = x @ proj_w + proj_b  (M=NN, N=512, K=256) ----
    cvt_split_kernel<<<(NN * 256 / 4 + 255) / 256, 256>>>(x, Ah, Al, NN * 256 / 4);
    cvt_transpose_kernel<<<dim3(512 / 32, 256 / 32), dim3(32, 8)>>>(proj_w, Wh, Wl, 256, 512);
    run_gemm(Ah, Al, Wh, Wl, proj_b, h0, NN, 512, 256);

    // ---- GAT layer 1 (H=4, C=512, concat, ELU): N=2048, K=512 ----
    cvt_split_kernel<<<(NN * 512 / 4 + 255) / 256, 256>>>(h0, Ah, Al, NN * 512 / 4);
    cvt_transpose_kernel<<<dim3(2048 / 32, 512 / 32), dim3(32, 8)>>>(w1, Wh, Wl, 512, 2048);
    run_gemm(Ah, Al, Wh, Wl, nullptr, hmat, NN, 2048, 512);
    attn_kernel<<<NN, 128>>>(hmat, as1, ad1, 4);
    softmax_kernel<<<(NN * 4 + 255) / 256, 256>>>(4);
    aggregate_kernel<2048, 0><<<NN, 256>>>(hmat, b1, bufA);

    // ---- GAT layer 2 (H=4, C=512, concat, ELU): N=2048, K=2048 ----
    cvt_split_kernel<<<(NN * 2048 / 4 + 255) / 256, 256>>>(bufA, Ah, Al, NN * 2048 / 4);
    cvt_transpose_kernel<<<dim3(2048 / 32, 2048 / 32), dim3(32, 8)>>>(w2, Wh, Wl, 2048, 2048);
    run_gemm(Ah, Al, Wh, Wl, nullptr, hmat, NN, 2048, 2048);
    attn_kernel<<<NN, 128>>>(hmat, as2, ad2, 4);
    softmax_kernel<<<(NN * 4 + 255) / 256, 256>>>(4);
    aggregate_kernel<2048, 0><<<NN, 256>>>(hmat, b2, bufB);

    // ---- GAT layer 3 (H=2, C=512, mean): N=1024, K=2048 ----
    cvt_split_kernel<<<(NN * 2048 / 4 + 255) / 256, 256>>>(bufB, Ah, Al, NN * 2048 / 4);
    cvt_transpose_kernel<<<dim3(1024 / 32, 2048 / 32), dim3(32, 8)>>>(w3, Wh, Wl, 2048, 1024);
    run_gemm(Ah, Al, Wh, Wl, nullptr, hmat, NN, 1024, 2048);
    attn_kernel<<<NN, 64>>>(hmat, as3, ad3, 2);
    softmax_kernel<<<(NN * 2 + 255) / 256, 256>>>(2);
    aggregate_kernel<1024, 1><<<NN, 256>>>(hmat, b3, out);
}